// round 10
// baseline (speedup 1.0000x reference)
#include <cuda_runtime.h>
#include <cuda_bf16.h>
#include <cstdint>

// ---------------- problem constants ----------------
#define NROW 8192
#define KDIM 64
#define NAUG 72
#define NTILES 9                 // 72 / 8
#define TILE_M 128
#define KC 32                    // K per chunk (2 x k16 fragments)
#define SPLITS 8
#define KSPLIT (NROW / SPLITS)   // 1024
#define NCHUNK (KSPLIT / KC)     // 32
#define NTHREADS 128
#define MTILES (NROW / TILE_M)   // 64
#define BFRAG_BYTES (NTILES * 256)     // 2304 bytes per k16 fragment block
#define NPART (MTILES * SPLITS)  // 512
#define ASTRIDE 40               // A row stride in floats (LDS.64 conflict-free)
#define NSTAGE 3
#define STAGE_FLOATS (TILE_M * ASTRIDE)          // 5120 floats = 20480 B
#define SMEM_BYTES (NSTAGE * STAGE_FLOATS * 4)   // 61440 B

// ---------------- device scratch ----------------
__device__ float g_sq[NROW];
__device__ __align__(16) unsigned char g_yaugB[(NROW / 16) * BFRAG_BYTES];  // 1.18 MB packed bf16
__device__ float g_part[NPART];
__device__ unsigned int g_cnt = 0;

// ---------------- helpers ----------------
__device__ __forceinline__ uint32_t smem_to_u32(const void* p) {
    uint32_t a;
    asm("{ .reg .u64 t; cvta.to.shared.u64 t, %1; cvt.u32.u64 %0, t; }" : "=r"(a) : "l"(p));
    return a;
}
__device__ __forceinline__ uint32_t pack_bf16x2(float lo, float hi) {
    uint32_t r;
    asm("cvt.rn.bf16x2.f32 %0, %1, %2;" : "=r"(r) : "f"(hi), "f"(lo));
    return r;
}
__device__ __forceinline__ void cpa16(uint32_t dst_smem, const void* src_gmem) {
    asm volatile("cp.async.cg.shared.global [%0], [%1], 16;" :: "r"(dst_smem), "l"(src_gmem));
}
#define CP_COMMIT() asm volatile("cp.async.commit_group;" ::: "memory")
#define CP_WAIT2()  asm volatile("cp.async.wait_group 2;" ::: "memory")

__device__ __forceinline__ void mma_bf16(float* c, const uint32_t* a, uint32_t b0, uint32_t b1) {
    asm volatile(
        "mma.sync.aligned.m16n8k16.row.col.f32.bf16.bf16.f32 "
        "{%0,%1,%2,%3},{%4,%5,%6,%7},{%8,%9},{%0,%1,%2,%3};"
        : "+f"(c[0]), "+f"(c[1]), "+f"(c[2]), "+f"(c[3])
        : "r"(a[0]), "r"(a[1]), "r"(a[2]), "r"(a[3]), "r"(b0), "r"(b1));
}

// byte offset of element (kg, n) inside g_yaugB (fragment-register layout)
__device__ __forceinline__ uint32_t b_offset(int kg, int n) {
    int frag = kg >> 4;           // global k16 fragment index
    int kl   = kg & 15;
    int nt   = n >> 3;
    int n8   = n & 7;
    int lane = n8 * 4 + ((kl & 7) >> 1);
    return (uint32_t)((frag * NTILES + nt) * 256 + lane * 8
                      + ((kl >> 3) & 1) * 4 + (kl & 1) * 2);
}

// ---------------- prep: sq + fragment-packed bf16 Yaug ----------------
__global__ void prep(const float* __restrict__ Y) {
    int w    = (blockIdx.x * blockDim.x + threadIdx.x) >> 5;
    int lane = threadIdx.x & 31;
    if (w >= NROW) return;
    if (w == 0 && lane == 0) g_cnt = 0;

    const float* yr = Y + (size_t)w * KDIM;
    float v0 = yr[lane], v1 = yr[lane + 32];
    float s = v0 * v0 + v1 * v1;
#pragma unroll
    for (int o = 16; o; o >>= 1) s += __shfl_xor_sync(0xffffffffu, s, o);
    if (lane == 0) g_sq[w] = s;

    *reinterpret_cast<__nv_bfloat16*>(g_yaugB + b_offset(w, lane))      = __float2bfloat16_rn(v0);
    *reinterpret_cast<__nv_bfloat16*>(g_yaugB + b_offset(w, lane + 32)) = __float2bfloat16_rn(v1);
    if (lane < 8) {
        float v = (lane == 0) ? 1.0f : (lane == 1) ? s : 0.0f;
        *reinterpret_cast<__nv_bfloat16*>(g_yaugB + b_offset(w, 64 + lane)) = __float2bfloat16_rn(v);
    }
}

// ---------------- main: R3 skeleton + 3-stage depth-2 pipeline, B via ldg ----------------
// CTA-wide cooperative A loads, issue-before-wait, 2 barriers/chunk (R3 structure),
// but with 3 stages so 2 full chunks remain in flight during every compute phase.
__global__ __launch_bounds__(NTHREADS, 4)
void spectral_main(const float* __restrict__ W, const float* __restrict__ Y,
                   float* __restrict__ out) {
    extern __shared__ __align__(16) float smf[];
    const int tid  = threadIdx.x;
    const int wid  = tid >> 5;
    const int lane = tid & 31;
    const int g    = lane >> 2;
    const int tg   = lane & 3;
    const int m0   = blockIdx.x * TILE_M;
    const int kbase = blockIdx.y * KSPLIT;

    const uint32_t sb = smem_to_u32(smf);
    const float* wsrc = W + (size_t)m0 * NROW + kbase;
    const unsigned char* bsplit = g_yaugB + (size_t)(kbase >> 4) * BFRAG_BYTES;

    float acc[2][NTILES][4];
#pragma unroll
    for (int mf = 0; mf < 2; ++mf)
#pragma unroll
        for (int nt = 0; nt < NTILES; ++nt)
#pragma unroll
            for (int q = 0; q < 4; ++q) acc[mf][nt][q] = 0.0f;

    // CTA-wide cooperative A load: 128x32 fp32 = 1024 float4, 8 per thread,
    // rows 128B-coalesced (8 lanes x 16B per row).
    auto loadA = [&](int t, int stage) {
        const float* src = wsrc + t * KC;
        const uint32_t dst = sb + (uint32_t)stage * (STAGE_FLOATS * 4);
#pragma unroll
        for (int j = 0; j < 8; ++j) {
            int f = tid + j * NTHREADS;
            int row = f >> 3, c4 = f & 7;
            cpa16(dst + (uint32_t)(row * ASTRIDE + c4 * 4) * 4,
                  src + (size_t)row * NROW + c4 * 4);
        }
        CP_COMMIT();
    };

    loadA(0, 0);
    loadA(1, 1);

    int s2 = 2;   // (t+2) % 3, tracked incrementally
    for (int t = 0; t < NCHUNK; ++t) {
        // Issue chunk t+2 BEFORE waiting: stage (t+2)%3 was consumed at t-1 and is
        // protected by iteration t-1's trailing barrier. Loads enter LSU pre-stall.
        if (t + 2 < NCHUNK) loadA(t + 2, s2);
        else                CP_COMMIT();          // uniform group accounting
        s2 = (s2 == 2) ? 0 : s2 + 1;

        CP_WAIT2();            // own groups: t done (t+1, t+2 in flight)
        __syncthreads();       // all warps' portions of stage t complete & visible

        const float* ab = smf + (size_t)(t % 3) * STAGE_FLOATS;
        const unsigned char* bch = bsplit + (size_t)(2 * t) * BFRAG_BYTES;

#pragma unroll
        for (int ks = 0; ks < 2; ++ks) {
            // B fragments (L2/L1-resident packed global, 256B-coalesced)
            uint2 b[NTILES];
#pragma unroll
            for (int nt = 0; nt < NTILES; ++nt)
                b[nt] = __ldg(reinterpret_cast<const uint2*>(
                    bch + (size_t)ks * BFRAG_BYTES + nt * 256 + lane * 8));

            // A fragments: LDS.64 conflict-free (stride 40), fp32 -> bf16x2
            uint32_t abf[2][4];
#pragma unroll
            for (int mf = 0; mf < 2; ++mf) {
                int rb = wid * 32 + mf * 16;
                int cb = ks * 16 + tg * 2;
                float2 v0 = *reinterpret_cast<const float2*>(ab + (rb + g)     * ASTRIDE + cb);
                float2 v1 = *reinterpret_cast<const float2*>(ab + (rb + g + 8) * ASTRIDE + cb);
                float2 v2 = *reinterpret_cast<const float2*>(ab + (rb + g)     * ASTRIDE + cb + 8);
                float2 v3 = *reinterpret_cast<const float2*>(ab + (rb + g + 8) * ASTRIDE + cb + 8);
                abf[mf][0] = pack_bf16x2(v0.x, v0.y);
                abf[mf][1] = pack_bf16x2(v1.x, v1.y);
                abf[mf][2] = pack_bf16x2(v2.x, v2.y);
                abf[mf][3] = pack_bf16x2(v3.x, v3.y);
            }
#pragma unroll
            for (int nt = 0; nt < NTILES; ++nt) {
                mma_bf16(acc[0][nt], abf[0], b[nt].x, b[nt].y);
                mma_bf16(acc[1][nt], abf[1], b[nt].x, b[nt].y);
            }
        }
        __syncthreads();       // trailing: stage t free for reuse at iteration t+1's issue
    }

    // ---- epilogue: contract Z fragments against coefficients ----
    float partial = 0.0f;
#pragma unroll
    for (int mf = 0; mf < 2; ++mf) {
#pragma unroll
        for (int half = 0; half < 2; ++half) {
            int i = m0 + wid * 32 + mf * 16 + half * 8 + g;
            const float* yr = Y + (size_t)i * KDIM;
            float s = 0.0f;
#pragma unroll
            for (int nt = 0; nt < 8; ++nt) {
                int col = nt * 8 + tg * 2;
                s = fmaf(yr[col],     acc[mf][nt][half * 2 + 0], s);
                s = fmaf(yr[col + 1], acc[mf][nt][half * 2 + 1], s);
            }
            float e = -2.0f * s;
            if (tg == 0) {
                e = fmaf(g_sq[i], acc[mf][8][half * 2 + 0], e);
                e += acc[mf][8][half * 2 + 1];
            }
            partial += e;
        }
    }
#pragma unroll
    for (int o = 16; o; o >>= 1) partial += __shfl_xor_sync(0xffffffffu, partial, o);

    __shared__ float red[8];
    __shared__ int flag;
    if (lane == 0) red[wid] = partial;
    __syncthreads();

    // ---- last-block deterministic final reduction ----
    if (tid == 0) {
        g_part[blockIdx.y * MTILES + blockIdx.x] = red[0] + red[1] + red[2] + red[3];
        __threadfence();
        unsigned int old = atomicAdd(&g_cnt, 1u);
        flag = (old == NPART - 1) ? 1 : 0;
    }
    __syncthreads();
    if (flag) {
        __threadfence();
        float s = g_part[tid] + g_part[tid + 128] + g_part[tid + 256] + g_part[tid + 384];
#pragma unroll
        for (int o = 16; o; o >>= 1) s += __shfl_xor_sync(0xffffffffu, s, o);
        if (lane == 0) red[wid] = s;
        __syncthreads();
        if (tid == 0) {
            out[0] = (red[0] + red[1] + red[2] + red[3]) * (1.0f / (2.0f * (float)NROW));
            g_cnt = 0;
        }
    }
}

// ---------------- launch ----------------
extern "C" void kernel_launch(void* const* d_in, const int* in_sizes, int n_in,
                              void* d_out, int out_size) {
    const float* W;
    const float* Y;
    if (in_sizes[0] == NROW * NROW) {
        W = (const float*)d_in[0];
        Y = (const float*)d_in[1];
    } else {
        Y = (const float*)d_in[0];
        W = (const float*)d_in[1];
    }
    cudaFuncSetAttribute(spectral_main, cudaFuncAttributeMaxDynamicSharedMemorySize, SMEM_BYTES);

    prep<<<NROW / 8, 256>>>(Y);
    spectral_main<<<dim3(MTILES, SPLITS), NTHREADS, SMEM_BYTES>>>(W, Y, (float*)d_out);
}

// round 11
// speedup vs baseline: 1.4938x; 1.4938x over previous
#include <cuda_runtime.h>
#include <cuda_bf16.h>
#include <cstdint>

// ---------------- problem constants ----------------
#define NROW 8192
#define KDIM 64
#define NAUG 72
#define NTILES 9                 // 72 / 8
#define TILE_M 128
#define KC 32                    // K per chunk (2 x k16 fragments)
#define NTHREADS 128
#define MTILES (NROW / TILE_M)   // 64
#define NGCHUNK (NROW / KC)      // 256 global k-chunks
#define NSPLIT 9                 // uneven k-splits: 4x29 + 5x28 = 256
#define NPART (MTILES * NSPLIT)  // 576
#define ASTRIDE 40               // A row stride in floats (LDS.64 conflict-free)
#define BCH_BYTES (2 * NTILES * 256)   // 4608 bytes per B chunk

// ---------------- device scratch ----------------
__device__ float g_sq[NROW];
__device__ __align__(16) unsigned char g_yaugB[NGCHUNK * BCH_BYTES];  // 1.18 MB packed bf16
__device__ float g_part[NPART];
__device__ unsigned int g_cnt = 0;

// ---------------- helpers ----------------
__device__ __forceinline__ uint32_t smem_to_u32(const void* p) {
    uint32_t a;
    asm("{ .reg .u64 t; cvta.to.shared.u64 t, %1; cvt.u32.u64 %0, t; }" : "=r"(a) : "l"(p));
    return a;
}
__device__ __forceinline__ uint32_t pack_bf16x2(float lo, float hi) {
    uint32_t r;
    asm("cvt.rn.bf16x2.f32 %0, %1, %2;" : "=r"(r) : "f"(hi), "f"(lo));
    return r;
}
__device__ __forceinline__ void cpa16(uint32_t dst_smem, const void* src_gmem) {
    asm volatile("cp.async.cg.shared.global [%0], [%1], 16;" :: "r"(dst_smem), "l"(src_gmem));
}
#define CP_COMMIT() asm volatile("cp.async.commit_group;" ::: "memory")
#define CP_WAIT1()  asm volatile("cp.async.wait_group 1;" ::: "memory")
#define CP_WAIT0()  asm volatile("cp.async.wait_group 0;" ::: "memory")

__device__ __forceinline__ void mma_bf16(float* c, const uint32_t* a, uint32_t b0, uint32_t b1) {
    asm volatile(
        "mma.sync.aligned.m16n8k16.row.col.f32.bf16.bf16.f32 "
        "{%0,%1,%2,%3},{%4,%5,%6,%7},{%8,%9},{%0,%1,%2,%3};"
        : "+f"(c[0]), "+f"(c[1]), "+f"(c[2]), "+f"(c[3])
        : "r"(a[0]), "r"(a[1]), "r"(a[2]), "r"(a[3]), "r"(b0), "r"(b1));
}

// byte offset of element (kg, n) inside g_yaugB (fragment-register layout)
__device__ __forceinline__ uint32_t b_offset(int kg, int n) {
    int gc  = kg >> 5;            // global 32-chunk
    int k16 = (kg >> 4) & 1;      // k16 fragment within chunk
    int kl  = kg & 15;
    int nt  = n >> 3;
    int n8  = n & 7;
    int lane = n8 * 4 + ((kl & 7) >> 1);
    return (uint32_t)(((gc * 2 + k16) * NTILES + nt) * 256 + lane * 8
                      + ((kl >> 3) & 1) * 4 + (kl & 1) * 2);
}

// ---------------- SMEM layout (bytes) — identical to R3 champion ----------------
#define SMEM_A0   0
#define SMEM_A1   (TILE_M * ASTRIDE * 4)               // 20480
#define SMEM_B0   (2 * TILE_M * ASTRIDE * 4)           // 40960
#define SMEM_B1   (SMEM_B0 + BCH_BYTES)                // 45568
#define SMEM_BYTES (SMEM_B1 + BCH_BYTES)               // 50176

// ---------------- prep: sq + fragment-packed bf16 Yaug ----------------
__global__ void prep(const float* __restrict__ Y) {
    int w    = (blockIdx.x * blockDim.x + threadIdx.x) >> 5;
    int lane = threadIdx.x & 31;
    if (w >= NROW) return;
    if (w == 0 && lane == 0) g_cnt = 0;

    const float* yr = Y + (size_t)w * KDIM;
    float v0 = yr[lane], v1 = yr[lane + 32];
    float s = v0 * v0 + v1 * v1;
#pragma unroll
    for (int o = 16; o; o >>= 1) s += __shfl_xor_sync(0xffffffffu, s, o);
    if (lane == 0) g_sq[w] = s;

    *reinterpret_cast<__nv_bfloat16*>(g_yaugB + b_offset(w, lane))      = __float2bfloat16_rn(v0);
    *reinterpret_cast<__nv_bfloat16*>(g_yaugB + b_offset(w, lane + 32)) = __float2bfloat16_rn(v1);
    if (lane < 8) {
        float v = (lane == 0) ? 1.0f : (lane == 1) ? s : 0.0f;
        *reinterpret_cast<__nv_bfloat16*>(g_yaugB + b_offset(w, 64 + lane)) = __float2bfloat16_rn(v);
    }
}

// ---------------- main: R3 champion loop, 9 uneven k-splits, fused reduction ----------------
__global__ __launch_bounds__(NTHREADS, 4)
void spectral_main(const float* __restrict__ W, const float* __restrict__ Y,
                   float* __restrict__ out) {
    extern __shared__ __align__(16) char smem[];
    float* smf = reinterpret_cast<float*>(smem);
    const uint32_t sb = smem_to_u32(smem);

    const int tid  = threadIdx.x;
    const int wid  = tid >> 5;
    const int lane = tid & 31;
    const int g    = lane >> 2;
    const int tg   = lane & 3;
    const int m0   = blockIdx.x * TILE_M;

    // Uneven split: split by handles chunks [cs, cs+count): 29 for by<4, else 28.
    const int by    = blockIdx.y;
    const int cs    = 28 * by + ((by < 4) ? by : 4);
    const int count = 28 + (by < 4 ? 1 : 0);
    const int kbase = cs * KC;

    float acc[2][NTILES][4];
#pragma unroll
    for (int mf = 0; mf < 2; ++mf)
#pragma unroll
        for (int nt = 0; nt < NTILES; ++nt)
#pragma unroll
            for (int q = 0; q < 4; ++q) acc[mf][nt][q] = 0.0f;

    // ---- async load of one chunk into buffer (t&1) — exactly R3 ----
    auto load_chunk = [&](int t) {
        const uint32_t ab = sb + ((t & 1) ? SMEM_A1 : SMEM_A0);
        const uint32_t bb = sb + ((t & 1) ? SMEM_B1 : SMEM_B0);
        const int k0 = kbase + t * KC;
        // A: W tile 128 x 32 fp32 = 1024 float4; 8 per thread (128B-coalesced rows)
#pragma unroll
        for (int j = 0; j < 8; ++j) {
            int f = tid + j * NTHREADS;
            int r = f >> 3, c4 = f & 7;
            cpa16(ab + (uint32_t)(r * ASTRIDE + c4 * 4) * 4,
                  W + (size_t)(m0 + r) * NROW + k0 + c4 * 4);
        }
        // B: fragment-packed chunk, 4608 B = 288 float4 (L2-resident)
        const unsigned char* bsrc = g_yaugB + (size_t)(k0 >> 5) * BCH_BYTES;
#pragma unroll
        for (int j = 0; j < 3; ++j) {
            int f = tid + j * NTHREADS;
            if (f < 288) cpa16(bb + (uint32_t)f * 16, bsrc + (size_t)f * 16);
        }
        CP_COMMIT();
    };

    load_chunk(0);

    for (int t = 0; t < count; ++t) {
        if (t + 1 < count) { load_chunk(t + 1); CP_WAIT1(); }
        else               { CP_WAIT0(); }
        __syncthreads();

        const float* abuf = smf + ((t & 1) ? SMEM_A1 : SMEM_A0) / 4;
        const char*  bbuf = smem + ((t & 1) ? SMEM_B1 : SMEM_B0);

#pragma unroll
        for (int ks = 0; ks < 2; ++ks) {
            uint32_t a[2][4];
#pragma unroll
            for (int mf = 0; mf < 2; ++mf) {
                int rb = wid * 32 + mf * 16;
                int cb = ks * 16 + tg * 2;
                float2 v0 = *reinterpret_cast<const float2*>(abuf + (rb + g)     * ASTRIDE + cb);
                float2 v1 = *reinterpret_cast<const float2*>(abuf + (rb + g + 8) * ASTRIDE + cb);
                float2 v2 = *reinterpret_cast<const float2*>(abuf + (rb + g)     * ASTRIDE + cb + 8);
                float2 v3 = *reinterpret_cast<const float2*>(abuf + (rb + g + 8) * ASTRIDE + cb + 8);
                a[mf][0] = pack_bf16x2(v0.x, v0.y);
                a[mf][1] = pack_bf16x2(v1.x, v1.y);
                a[mf][2] = pack_bf16x2(v2.x, v2.y);
                a[mf][3] = pack_bf16x2(v3.x, v3.y);
            }
#pragma unroll
            for (int nt = 0; nt < NTILES; ++nt) {
                uint2 b = *reinterpret_cast<const uint2*>(
                    bbuf + (ks * NTILES + nt) * 256 + lane * 8);
                mma_bf16(acc[0][nt], a[0], b.x, b.y);
                mma_bf16(acc[1][nt], a[1], b.x, b.y);
            }
        }
        __syncthreads();
    }

    // ---- epilogue: contract Z fragments against coefficients ----
    float partial = 0.0f;
#pragma unroll
    for (int mf = 0; mf < 2; ++mf) {
#pragma unroll
        for (int half = 0; half < 2; ++half) {
            int i = m0 + wid * 32 + mf * 16 + half * 8 + g;
            const float* yr = Y + (size_t)i * KDIM;
            float s = 0.0f;
#pragma unroll
            for (int nt = 0; nt < 8; ++nt) {
                int col = nt * 8 + tg * 2;
                s = fmaf(yr[col],     acc[mf][nt][half * 2 + 0], s);
                s = fmaf(yr[col + 1], acc[mf][nt][half * 2 + 1], s);
            }
            float e = -2.0f * s;
            if (tg == 0) {
                e = fmaf(g_sq[i], acc[mf][8][half * 2 + 0], e);
                e += acc[mf][8][half * 2 + 1];
            }
            partial += e;
        }
    }
#pragma unroll
    for (int o = 16; o; o >>= 1) partial += __shfl_xor_sync(0xffffffffu, partial, o);

    __shared__ float red[8];
    __shared__ int flag;
    if (lane == 0) red[wid] = partial;
    __syncthreads();

    // ---- last-block deterministic final reduction (576 partials) ----
    if (tid == 0) {
        g_part[blockIdx.y * MTILES + blockIdx.x] = red[0] + red[1] + red[2] + red[3];
        __threadfence();
        unsigned int old = atomicAdd(&g_cnt, 1u);
        flag = (old == NPART - 1) ? 1 : 0;
    }
    __syncthreads();
    if (flag) {
        __threadfence();
        float s = g_part[tid] + g_part[tid + 128] + g_part[tid + 256] + g_part[tid + 384];
        if (tid < 64) s += g_part[tid + 512];
#pragma unroll
        for (int o = 16; o; o >>= 1) s += __shfl_xor_sync(0xffffffffu, s, o);
        if (lane == 0) red[wid] = s;
        __syncthreads();
        if (tid == 0) {
            out[0] = (red[0] + red[1] + red[2] + red[3]) * (1.0f / (2.0f * (float)NROW));
            g_cnt = 0;
        }
    }
}

// ---------------- launch ----------------
extern "C" void kernel_launch(void* const* d_in, const int* in_sizes, int n_in,
                              void* d_out, int out_size) {
    const float* W;
    const float* Y;
    if (in_sizes[0] == NROW * NROW) {
        W = (const float*)d_in[0];
        Y = (const float*)d_in[1];
    } else {
        Y = (const float*)d_in[0];
        W = (const float*)d_in[1];
    }
    cudaFuncSetAttribute(spectral_main, cudaFuncAttributeMaxDynamicSharedMemorySize, SMEM_BYTES);

    prep<<<NROW / 8, 256>>>(Y);
    spectral_main<<<dim3(MTILES, NSPLIT), NTHREADS, SMEM_BYTES>>>(W, Y, (float*)d_out);
}